// round 4
// baseline (speedup 1.0000x reference)
#include <cuda_runtime.h>

// HEALPix padding: data [B*12, 256, 64, 64] f32, p=2 -> out [B*12, 256, 68, 68].
//
// uint16 table enc = face<<12 | offset for border positions; center quads
// compute their source analytically (contiguous, no table). Fast paths load
// 2x float2 instead of 4 scalar LDGs. Blended diagonal positions (equator
// _tl/_br corners) are overwritten by a tiny fixup kernel.

#define HH 64
#define P  2
#define PH 68
#define PW 68
#define NPLANE (PH*PW)        // 4624
#define NQPP   (NPLANE/4)     // 1156
#define NC  256
#define NFACE 12
#define NTAB (NFACE*NPLANE)

__device__ unsigned short g_tab16[NTAB];

__device__ __forceinline__ int idx64(int r, int c) { return r * HH + c; }

__global__ void build_table_kernel() {
    int t = blockIdx.x * blockDim.x + threadIdx.x;
    if (t >= NTAB) return;
    int f   = t / NPLANE;
    int rem = t - f * NPLANE;
    int i   = rem / PW;
    int j   = rem - i * PW;

    int ii = i - P;
    int jj = j - P;
    int rb = i - P - HH;
    int jr = j - P - HH;

    int f1 = 0, o1 = 0;

    if (f < 4) {
        // north faces: _pn
        int n   = f;
        int Ft  = (n + 1) & 3;
        int Ftl = (n + 2) & 3;
        int Fl  = (n + 3) & 3;
        int Fbl = (n + 3) & 3;
        int Fb  = n + 4;
        int Fbr = n + 8;
        int Fr  = 4 + ((n + 1) & 3);
        int Ftr = (n + 1) & 3;
        if (i < P) {
            if (j < P)            { f1 = Ftl; o1 = idx64(P-1-i, P-1-j); }
            else if (j < P + HH)  { f1 = Ft;  o1 = idx64(jj, P-1-i); }
            else                  { f1 = Ftr; o1 = idx64(HH-P+i, jr); }
        } else if (i < P + HH) {
            if (j < P)            { f1 = Fl;  o1 = idx64(P-1-j, ii); }
            else if (j < P + HH)  { f1 = n;   o1 = idx64(ii, jj); }
            else                  { f1 = Fr;  o1 = idx64(ii, jr); }
        } else {
            if (j < P)            { f1 = Fbl; o1 = idx64(rb, HH-P+j); }
            else if (j < P + HH)  { f1 = Fb;  o1 = idx64(rb, jj); }
            else                  { f1 = Fbr; o1 = idx64(rb, jr); }
        }
    } else if (f < 8) {
        // equator faces: _pe (blend diagonals store src1; fixup overwrites)
        int k   = f - 4;
        int Ft  = k;
        int Fl  = (k + 3) & 3;
        int Fbl = 4 + ((k + 3) & 3);
        int Fb  = 8 + ((k + 3) & 3);
        int Fr  = 8 + k;
        int Ftr = 4 + ((k + 1) & 3);
        if (i < P) {
            if (j < P) {
                if (i == j)       { f1 = Ft; o1 = idx64(HH-P+i, 0); }
                else if (j > i)   { f1 = Ft; o1 = idx64(HH-P+i, j-i-1); }
                else              { f1 = Fl; o1 = idx64(i-j-1, HH-P+j); }
            }
            else if (j < P + HH)  { f1 = Ft;  o1 = idx64(HH-P+i, jj); }
            else                  { f1 = Ftr; o1 = idx64(HH-P+i, jr); }
        } else if (i < P + HH) {
            if (j < P)            { f1 = Fl;  o1 = idx64(ii, HH-P+j); }
            else if (j < P + HH)  { f1 = f;   o1 = idx64(ii, jj); }
            else                  { f1 = Fr;  o1 = idx64(ii, jr); }
        } else {
            if (j < P)            { f1 = Fbl; o1 = idx64(rb, HH-P+j); }
            else if (j < P + HH)  { f1 = Fb;  o1 = idx64(rb, jj); }
            else {
                if (rb == jr)     { f1 = Fb; o1 = idx64(rb, HH-1); }
                else if (jr < rb) { f1 = Fb; o1 = idx64(rb, HH-rb+jr); }
                else              { f1 = Fr; o1 = idx64(HH-jr+rb, jr); }
            }
        }
    } else {
        // south faces: _ps
        int m   = f - 8;
        int Ft  = 4 + ((m + 1) & 3);
        int Ftl = m;
        int Fl  = 4 + m;
        int Fbl = 8 + ((m + 3) & 3);
        int Fb  = 8 + ((m + 3) & 3);
        int Fbr = 8 + ((m + 2) & 3);
        int Fr  = 8 + ((m + 1) & 3);
        int Ftr = 8 + ((m + 1) & 3);
        if (i < P) {
            if (j < P)            { f1 = Ftl; o1 = idx64(HH-P+i, HH-P+j); }
            else if (j < P + HH)  { f1 = Ft;  o1 = idx64(HH-P+i, jj); }
            else                  { f1 = Ftr; o1 = idx64(HH-P+i, jr); }
        } else if (i < P + HH) {
            if (j < P)            { f1 = Fl;  o1 = idx64(ii, HH-P+j); }
            else if (j < P + HH)  { f1 = f;   o1 = idx64(ii, jj); }
            else                  { f1 = Fr;  o1 = idx64(HH-1-jr, ii); }
        } else {
            if (j < P)            { f1 = Fbl; o1 = idx64(rb, HH-P+j); }
            else if (j < P + HH)  { f1 = Fb;  o1 = idx64(jj, HH-1-rb); }
            else                  { f1 = Fbr; o1 = idx64(HH-1-rb, HH-1-jr); }
        }
    }

    g_tab16[t] = (unsigned short)((f1 << 12) | o1);
}

__global__ __launch_bounds__(256)
void pad_kernel(const float* __restrict__ in, float* __restrict__ out, int nquads) {
    int q = blockIdx.x * blockDim.x + threadIdx.x;
    if (q >= nquads) return;

    int posq = q % NQPP;
    int rest = q / NQPP;          // bf*NC + ch
    int ch   = rest & (NC - 1);
    int bf   = rest >> 8;
    int b    = bf / NFACE;
    int fo   = bf - b * NFACE;

    int i  = posq / 17;           // 17 quads per output row
    int j0 = (posq - i * 17) * 4;

    int sbase = ((b * NFACE) << 20) | (ch << 12);

    float4 v;
    if (i >= P && i < P + HH && j0 >= 4 && j0 <= 60) {
        // center fast path: contiguous in own face, no table read.
        const float* src = in + sbase + (fo << 20) + (i - P) * HH + (j0 - P);
        float2 a = *reinterpret_cast<const float2*>(src);
        float2 c = *reinterpret_cast<const float2*>(src + 2);
        v = make_float4(a.x, a.y, c.x, c.y);
    } else {
        const ushort4 e = *reinterpret_cast<const ushort4*>(&g_tab16[fo * NPLANE + posq * 4]);
        int face = e.x >> 12;
        if ((e.w >> 12) == face && e.y == e.x + 1 && e.z == e.x + 2 &&
            e.w == e.x + 3 && !(e.x & 1)) {
            // contiguous run on another face (band rows etc.)
            const float* src = in + sbase + (face << 20) + (e.x & 4095);
            float2 a = *reinterpret_cast<const float2*>(src);
            float2 c = *reinterpret_cast<const float2*>(src + 2);
            v = make_float4(a.x, a.y, c.x, c.y);
        } else {
            v.x = in[sbase + ((e.x >> 12) << 20) + (e.x & 4095)];
            v.y = in[sbase + ((e.y >> 12) << 20) + (e.y & 4095)];
            v.z = in[sbase + ((e.z >> 12) << 20) + (e.z & 4095)];
            v.w = in[sbase + ((e.w >> 12) << 20) + (e.w & 4095)];
        }
    }

    reinterpret_cast<float4*>(out)[q] = v;
}

// Overwrite the 16 blended positions per (b, ch): equator faces k=0..3,
// plane positions (0,0),(1,1),(66,66),(67,67).
__global__ void fixup_kernel(const float* __restrict__ in, float* __restrict__ out, int n) {
    int t = blockIdx.x * blockDim.x + threadIdx.x;
    if (t >= n) return;                    // n = B * NC * 4 * 4
    int slot = t & 3;
    int k    = (t >> 2) & 3;
    int ch   = (t >> 4) & (NC - 1);
    int b    = t >> 12;

    int pos, fA, oA, fB, oB;
    if (slot == 0)      { pos = 0;            fA = k;              oA = idx64(HH-P, 0);   fB = (k+3)&3;        oB = idx64(0, HH-P); }
    else if (slot == 1) { pos = PW + 1;       fA = k;              oA = idx64(HH-1, 0);   fB = (k+3)&3;        oB = idx64(0, HH-1); }
    else if (slot == 2) { pos = 66*PW + 66;   fA = 8+((k+3)&3);    oA = idx64(0, HH-1);   fB = 8+k;            oB = idx64(HH-1, 0); }
    else                { pos = 67*PW + 67;   fA = 8+((k+3)&3);    oA = idx64(1, HH-1);   fB = 8+k;            oB = idx64(HH-1, 1); }

    int sbase = ((b * NFACE) << 20) | (ch << 12);
    float v = 0.5f * (in[sbase + (fA << 20) + oA] + in[sbase + (fB << 20) + oB]);

    long oidx = ((long)(b * NFACE + (4 + k)) * NC + ch) * NPLANE + pos;
    out[oidx] = v;
}

extern "C" void kernel_launch(void* const* d_in, const int* in_sizes, int n_in,
                              void* d_out, int out_size) {
    const float* in = (const float*)d_in[0];
    float* out = (float*)d_out;

    build_table_kernel<<<(NTAB + 255) / 256, 256>>>();

    int nquads = out_size / 4;                 // 96*256*68*68 / 4
    pad_kernel<<<(nquads + 255) / 256, 256>>>(in, out, nquads);

    int nb = (out_size / (NFACE * NC * NPLANE));   // B = 8
    int nfix = nb * NC * 4 * 4;
    fixup_kernel<<<(nfix + 255) / 256, 256>>>(in, out, nfix);
}

// round 5
// speedup vs baseline: 1.0104x; 1.0104x over previous
#include <cuda_runtime.h>

// HEALPix padding: data [B*12, 256, 64, 64] f32, p=2 -> out [B*12, 256, 68, 68].
//
// uint16 table enc = face<<12 | offset for border positions; center quads
// compute their source analytically (no table read). Blended diagonal
// positions (equator _tl/_br corners) are handled inline in the table path
// (they occur on exactly 4 quads per equator-face plane).

#define HH 64
#define P  2
#define PH 68
#define PW 68
#define NPLANE (PH*PW)        // 4624
#define NQPP   (NPLANE/4)     // 1156
#define NC  256
#define NFACE 12
#define NTAB (NFACE*NPLANE)

__device__ unsigned short g_tab16[NTAB];

__device__ __forceinline__ int idx64(int r, int c) { return r * HH + c; }

__global__ void build_table_kernel() {
    int t = blockIdx.x * blockDim.x + threadIdx.x;
    if (t >= NTAB) return;
    int f   = t / NPLANE;
    int rem = t - f * NPLANE;
    int i   = rem / PW;
    int j   = rem - i * PW;

    int ii = i - P;
    int jj = j - P;
    int rb = i - P - HH;
    int jr = j - P - HH;

    int f1 = 0, o1 = 0;

    if (f < 4) {
        // north faces: _pn
        int n   = f;
        int Ft  = (n + 1) & 3;
        int Ftl = (n + 2) & 3;
        int Fl  = (n + 3) & 3;
        int Fbl = (n + 3) & 3;
        int Fb  = n + 4;
        int Fbr = n + 8;
        int Fr  = 4 + ((n + 1) & 3);
        int Ftr = (n + 1) & 3;
        if (i < P) {
            if (j < P)            { f1 = Ftl; o1 = idx64(P-1-i, P-1-j); }
            else if (j < P + HH)  { f1 = Ft;  o1 = idx64(jj, P-1-i); }
            else                  { f1 = Ftr; o1 = idx64(HH-P+i, jr); }
        } else if (i < P + HH) {
            if (j < P)            { f1 = Fl;  o1 = idx64(P-1-j, ii); }
            else if (j < P + HH)  { f1 = n;   o1 = idx64(ii, jj); }
            else                  { f1 = Fr;  o1 = idx64(ii, jr); }
        } else {
            if (j < P)            { f1 = Fbl; o1 = idx64(rb, HH-P+j); }
            else if (j < P + HH)  { f1 = Fb;  o1 = idx64(rb, jj); }
            else                  { f1 = Fbr; o1 = idx64(rb, jr); }
        }
    } else if (f < 8) {
        // equator faces: _pe (blend diagonals store src1; pad blends inline)
        int k   = f - 4;
        int Ft  = k;
        int Fl  = (k + 3) & 3;
        int Fbl = 4 + ((k + 3) & 3);
        int Fb  = 8 + ((k + 3) & 3);
        int Fr  = 8 + k;
        int Ftr = 4 + ((k + 1) & 3);
        if (i < P) {
            if (j < P) {
                if (i == j)       { f1 = Ft; o1 = idx64(HH-P+i, 0); }
                else if (j > i)   { f1 = Ft; o1 = idx64(HH-P+i, j-i-1); }
                else              { f1 = Fl; o1 = idx64(i-j-1, HH-P+j); }
            }
            else if (j < P + HH)  { f1 = Ft;  o1 = idx64(HH-P+i, jj); }
            else                  { f1 = Ftr; o1 = idx64(HH-P+i, jr); }
        } else if (i < P + HH) {
            if (j < P)            { f1 = Fl;  o1 = idx64(ii, HH-P+j); }
            else if (j < P + HH)  { f1 = f;   o1 = idx64(ii, jj); }
            else                  { f1 = Fr;  o1 = idx64(ii, jr); }
        } else {
            if (j < P)            { f1 = Fbl; o1 = idx64(rb, HH-P+j); }
            else if (j < P + HH)  { f1 = Fb;  o1 = idx64(rb, jj); }
            else {
                if (rb == jr)     { f1 = Fb; o1 = idx64(rb, HH-1); }
                else if (jr < rb) { f1 = Fb; o1 = idx64(rb, HH-rb+jr); }
                else              { f1 = Fr; o1 = idx64(HH-jr+rb, jr); }
            }
        }
    } else {
        // south faces: _ps
        int m   = f - 8;
        int Ft  = 4 + ((m + 1) & 3);
        int Ftl = m;
        int Fl  = 4 + m;
        int Fbl = 8 + ((m + 3) & 3);
        int Fb  = 8 + ((m + 3) & 3);
        int Fbr = 8 + ((m + 2) & 3);
        int Fr  = 8 + ((m + 1) & 3);
        int Ftr = 8 + ((m + 1) & 3);
        if (i < P) {
            if (j < P)            { f1 = Ftl; o1 = idx64(HH-P+i, HH-P+j); }
            else if (j < P + HH)  { f1 = Ft;  o1 = idx64(HH-P+i, jj); }
            else                  { f1 = Ftr; o1 = idx64(HH-P+i, jr); }
        } else if (i < P + HH) {
            if (j < P)            { f1 = Fl;  o1 = idx64(ii, HH-P+j); }
            else if (j < P + HH)  { f1 = f;   o1 = idx64(ii, jj); }
            else                  { f1 = Fr;  o1 = idx64(HH-1-jr, ii); }
        } else {
            if (j < P)            { f1 = Fbl; o1 = idx64(rb, HH-P+j); }
            else if (j < P + HH)  { f1 = Fb;  o1 = idx64(jj, HH-1-rb); }
            else                  { f1 = Fbr; o1 = idx64(HH-1-rb, HH-1-jr); }
        }
    }

    g_tab16[t] = (unsigned short)((f1 << 12) | o1);
}

__global__ __launch_bounds__(256)
void pad_kernel(const float* __restrict__ in, float* __restrict__ out, int nquads) {
    int q = blockIdx.x * blockDim.x + threadIdx.x;
    if (q >= nquads) return;

    int posq = q % NQPP;
    int rest = q / NQPP;          // bf*NC + ch
    int ch   = rest & (NC - 1);
    int bf   = rest >> 8;
    int b    = bf / NFACE;
    int fo   = bf - b * NFACE;

    int i  = posq / 17;           // 17 quads per output row
    int jq = posq - i * 17;       // quad-in-row, j0 = jq*4

    int sbase = ((b * NFACE) << 20) | (ch << 12);

    float4 v;
    if ((unsigned)(i - P) < HH && (unsigned)(jq - 1) < 15) {
        // center fast path: contiguous in own face, no table read.
        const float* src = in + sbase + (fo << 20) + (i - P) * HH + (jq * 4 - P);
        v.x = __ldg(src + 0);
        v.y = __ldg(src + 1);
        v.z = __ldg(src + 2);
        v.w = __ldg(src + 3);
    } else {
        const ushort4 e = *reinterpret_cast<const ushort4*>(&g_tab16[fo * NPLANE + posq * 4]);
        v.x = __ldg(in + sbase + ((e.x >> 12) << 20) + (e.x & 4095));
        v.y = __ldg(in + sbase + ((e.y >> 12) << 20) + (e.y & 4095));
        v.z = __ldg(in + sbase + ((e.z >> 12) << 20) + (e.z & 4095));
        v.w = __ldg(in + sbase + ((e.w >> 12) << 20) + (e.w & 4095));

        // blended _tl/_br diagonal positions: equator faces only, 4 quads/plane
        if ((unsigned)(fo - 4) < 4) {
            int k = fo - 4;
            if (posq == 0) {            // (0,0) -> component x
                v.x = 0.5f * (__ldg(in + sbase + (k << 20)             + idx64(HH-P, 0)) +
                              __ldg(in + sbase + (((k+3)&3) << 20)     + idx64(0, HH-P)));
            } else if (posq == 17) {    // (1,1) -> component y
                v.y = 0.5f * (__ldg(in + sbase + (k << 20)             + idx64(HH-1, 0)) +
                              __ldg(in + sbase + (((k+3)&3) << 20)     + idx64(0, HH-1)));
            } else if (posq == 1138) {  // (66,66) -> component z
                v.z = 0.5f * (__ldg(in + sbase + ((8+((k+3)&3)) << 20) + idx64(0, HH-1)) +
                              __ldg(in + sbase + ((8+k) << 20)         + idx64(HH-1, 0)));
            } else if (posq == 1155) {  // (67,67) -> component w
                v.w = 0.5f * (__ldg(in + sbase + ((8+((k+3)&3)) << 20) + idx64(1, HH-1)) +
                              __ldg(in + sbase + ((8+k) << 20)         + idx64(HH-1, 1)));
            }
        }
    }

    __stcs(reinterpret_cast<float4*>(out) + q, v);
}

extern "C" void kernel_launch(void* const* d_in, const int* in_sizes, int n_in,
                              void* d_out, int out_size) {
    const float* in = (const float*)d_in[0];
    float* out = (float*)d_out;

    build_table_kernel<<<(NTAB + 255) / 256, 256>>>();

    int nquads = out_size / 4;                 // 96*256*68*68 / 4
    pad_kernel<<<(nquads + 255) / 256, 256>>>(in, out, nquads);
}